// round 16
// baseline (speedup 1.0000x reference)
#include <cuda_runtime.h>
#include <math.h>
#include <stdint.h>

#define BB 32
#define TT 4096
#define DD 1024
#define HH 16
#define DHEAD 64

// Scratch (device globals; no allocations)
__device__ float g_q[BB * DD];
__device__ float g_wqt[BB * HH * DD];   // wq~[b][h][i], tf32-rounded, incl /8
__device__ float g_sb[BB * HH];
__device__ float g_r[BB * HH * DD];     // r[b][h][i]
__device__ float g_ctx[BB * DD];
__device__ float g_pp[BB * 4 * DD];     // rowproj partials

// Persistent-kernel sync state (zeroed by rp_part block 0 each call)
__device__ int g_tk;          // global ticket counter
__device__ int g_sd[BB];      // scores tiles done per b
__device__ int g_smd[BB];     // softmax rows done per b
__device__ int g_rd[BB];      // rmix tiles done per b
__device__ int g_bc;          // count of b's with rmix fully done

#define TICKETS_PER_B 52      // 16 scores + 16 softmax + 16 rmix + 4 ctx
#define NTICKETS (BB * TICKETS_PER_B)   // 1664
#define BWINDOW 5
#define FUSED_GRID 444        // 3 per SM floor -> resident even at occ=3

// ---------------------------------------------------------------------------
__device__ __forceinline__ uint32_t f2tf32(float x) {
    uint32_t u;
    asm("cvt.rna.tf32.f32 %0, %1;" : "=r"(u) : "f"(x));
    return u;
}
__device__ __forceinline__ uint32_t smem_u32(const void* p) {
    uint32_t a;
    asm("{ .reg .u64 t; cvta.to.shared.u64 t, %1; cvt.u32.u64 %0, t; }"
        : "=r"(a) : "l"(p));
    return a;
}
__device__ __forceinline__ void cp_async16(uint32_t sdst, const void* gsrc) {
    asm volatile("cp.async.cg.shared.global [%0], [%1], 16;" :: "r"(sdst), "l"(gsrc));
}
#define CP_COMMIT() asm volatile("cp.async.commit_group;" ::: "memory")
#define CP_WAIT(n)  asm volatile("cp.async.wait_group %0;" :: "n"(n) : "memory")

__device__ __forceinline__ void mma_tf32(
    float* c, uint32_t a0, uint32_t a1, uint32_t a2, uint32_t a3,
    uint32_t b0, uint32_t b1) {
    asm volatile(
        "mma.sync.aligned.m16n8k8.row.col.f32.tf32.tf32.f32 "
        "{%0,%1,%2,%3}, {%4,%5,%6,%7}, {%8,%9}, {%0,%1,%2,%3};"
        : "+f"(c[0]), "+f"(c[1]), "+f"(c[2]), "+f"(c[3])
        : "r"(a0), "r"(a1), "r"(a2), "r"(a3), "r"(b0), "r"(b1));
}

__device__ __forceinline__ int ld_acquire(const int* p) {
    int v;
    asm volatile("ld.acquire.gpu.s32 %0, [%1];" : "=r"(v) : "l"(p) : "memory");
    return v;
}
// Block-wide wait until *cnt >= target (tid0 spins, barrier broadcasts).
__device__ __forceinline__ void spin_until(int* cnt, int target) {
    if (threadIdx.x == 0) {
        while (ld_acquire(cnt) < target) __nanosleep(128);
    }
    __syncthreads();
}
// All threads' prior writes visible, then tid0 increments counter.
__device__ __forceinline__ void mark_done(int* cnt) {
    __threadfence();
    __syncthreads();
    if (threadIdx.x == 0) atomicAdd(cnt, 1);
}

// ---------------------------------------------------------------------------
// Split row projection: partials over k-slices of 256, then reduce.
// rp_part block (0,0) also zeroes the persistent-kernel counters.
// ---------------------------------------------------------------------------
__global__ __launch_bounds__(256) void rp_part_kernel(
    const float* __restrict__ X, const float* __restrict__ W,
    float* __restrict__ pp) {
    __shared__ float xs[256];
    const int s = blockIdx.x;
    const int b = blockIdx.y;
    const int tid = threadIdx.x;
    if (s == 0 && b == 0 && tid == 0) {
        g_tk = 0; g_bc = 0;
        for (int i = 0; i < BB; i++) { g_sd[i] = 0; g_smd[i] = 0; g_rd[i] = 0; }
        __threadfence();
    }
    xs[tid] = X[(size_t)b * DD + s * 256 + tid];
    __syncthreads();
    float a0 = 0.f, a1 = 0.f, a2 = 0.f, a3 = 0.f;
#pragma unroll 8
    for (int k = 0; k < 256; k++) {
        const float xv = xs[k];
        const float* wr = W + (size_t)(s * 256 + k) * DD;
        a0 += xv * wr[tid];
        a1 += xv * wr[tid + 256];
        a2 += xv * wr[tid + 512];
        a3 += xv * wr[tid + 768];
    }
    float* o = pp + (size_t)(b * 4 + s) * DD;
    o[tid] = a0; o[tid + 256] = a1; o[tid + 512] = a2; o[tid + 768] = a3;
}

// Reduce partials; if bk != null also compute sb[b][h] = (1/8) bk_h . q_h
__global__ __launch_bounds__(256) void rp_reduce_kernel(
    const float* __restrict__ pp, const float* __restrict__ bias,
    float* __restrict__ Y, const float* __restrict__ bk,
    float* __restrict__ sbout) {
    __shared__ float hb[32];
    const int b = blockIdx.x;
    const int tid = threadIdx.x;
    const int w = tid >> 5, lane = tid & 31;
    float qv[4];
#pragma unroll
    for (int j = 0; j < 4; j++) {
        const int c = tid + j * 256;
        float s = bias[c];
#pragma unroll
        for (int sl = 0; sl < 4; sl++) s += pp[(size_t)(b * 4 + sl) * DD + c];
        Y[(size_t)b * DD + c] = s;
        qv[j] = s;
    }
    if (bk != nullptr) {
#pragma unroll
        for (int j = 0; j < 4; j++) {
            float p = qv[j] * bk[tid + j * 256] * 0.125f;
#pragma unroll
            for (int o = 16; o > 0; o >>= 1)
                p += __shfl_down_sync(0xFFFFFFFF, p, o);
            if (lane == 0) hb[(j * 4 + (w >> 1)) * 2 + (w & 1)] = p;
        }
        __syncthreads();
        if (tid < HH) sbout[b * HH + tid] = hb[tid * 2] + hb[tid * 2 + 1];
    }
}

// ---------------------------------------------------------------------------
// wq~[b][h][i] = tf32( (1/8) * sum_d Wk[i][h*64+d] * q[b][h*64+d] )
// ---------------------------------------------------------------------------
#define WQT_SMEM ((256 * 65 + 64) * 4)
__global__ __launch_bounds__(256) void wqt_kernel(
    const float* __restrict__ Wk, const float* __restrict__ q,
    float* __restrict__ wqt) {
    extern __shared__ float sm[];
    float* wk_s = sm;
    float* q_s  = sm + 256 * 65;
    const int tid = threadIdx.x;
    const int i0 = blockIdx.x * 256;
    const int b = blockIdx.y;

    float acc[HH];
#pragma unroll 1
    for (int h = 0; h < HH; h++) {
        __syncthreads();
        if (tid < 16)
            ((float4*)q_s)[tid] =
                ((const float4*)(q + (size_t)b * DD + h * DHEAD))[tid];
#pragma unroll
        for (int j = 0; j < 16; j++) {
            const int u = tid + j * 256;
            const int row = u >> 4, i4 = u & 15;
            float4 v = ((const float4*)Wk)[(size_t)(i0 + row) * 256 + h * 16 + i4];
            float* d = wk_s + row * 65 + i4 * 4;
            d[0] = v.x; d[1] = v.y; d[2] = v.z; d[3] = v.w;
        }
        __syncthreads();
        float s = 0.f;
        const float* wr = wk_s + tid * 65;
#pragma unroll 8
        for (int dd = 0; dd < 64; dd++) s += wr[dd] * q_s[dd];
        acc[h] = s * 0.125f;
    }
#pragma unroll
    for (int h = 0; h < HH; h++)
        wqt[((size_t)(b * HH + h)) * DD + i0 + tid] =
            __uint_as_float(f2tf32(acc[h]));
}

// ---------------------------------------------------------------------------
// Fused persistent kernel bodies
// ---------------------------------------------------------------------------

// scores tile: C[t0..t0+255, 16h] = matrix[b, t-tile] @ wq~T + sb
#define SCB_AS (256 * 8)
#define SCB_BS (16 * 8)
#define SCB_STAGE (SCB_AS + SCB_BS)   // 2176 floats
__device__ void scores_body(
    float* pool, const float* __restrict__ matrix,
    const float* __restrict__ wqt, const float* __restrict__ sb,
    float* __restrict__ scores_out, int b, int jt) {
    const uint32_t su0 = smem_u32(pool);
    const int tid = threadIdx.x;
    const int wid = tid >> 5;
    const int lid = tid & 31;
    const int g = lid >> 2, tig = lid & 3;
    const int t0 = jt * 256;
    const int wm = wid * 32;

    const char* matbase = (const char*)(matrix + (size_t)(b * TT + t0) * DD);
    const char* wqb = (const char*)(wqt + (size_t)b * HH * DD);

    auto issueChunk = [&](int c, int s) {
        const uint32_t au = su0 + (uint32_t)(s * SCB_STAGE * 4);
#pragma unroll
        for (int j = 0; j < 2; j++) {
            const int u = tid + j * 256;
            const int r = u >> 1, cu = u & 1;
            cp_async16(au + (uint32_t)(r * 32 + cu * 16),
                       matbase + (size_t)r * (DD * 4) + c * 32 + cu * 16);
        }
        if (tid < 32) {
            const int h = tid >> 1, k4 = tid & 1;
            cp_async16(au + (uint32_t)(SCB_AS * 4) + (uint32_t)(h * 32 + k4 * 16),
                       wqb + (size_t)h * (DD * 4) + c * 32 + k4 * 16);
        }
        CP_COMMIT();
    };

    float acc[2][2][4];
#pragma unroll
    for (int i = 0; i < 2; i++)
#pragma unroll
        for (int j = 0; j < 2; j++)
#pragma unroll
            for (int q = 0; q < 4; q++) acc[i][j][q] = 0.f;

    issueChunk(0, 0);
    issueChunk(1, 1);
    issueChunk(2, 2);
    issueChunk(3, 3);

    for (int c = 0; c < 128; c++) {
        const int s = c & 3;
        CP_WAIT(3);
        __syncthreads();
        const float* As_s = pool + s * SCB_STAGE;
        const float* Bs_s = As_s + SCB_AS;

        uint32_t af[2][4];
#pragma unroll
        for (int mf = 0; mf < 2; mf++) {
            const int rb = wm + mf * 16;
            af[mf][0] = f2tf32(As_s[(rb + g) * 8 + tig]);
            af[mf][1] = f2tf32(As_s[(rb + g + 8) * 8 + tig]);
            af[mf][2] = f2tf32(As_s[(rb + g) * 8 + tig + 4]);
            af[mf][3] = f2tf32(As_s[(rb + g + 8) * 8 + tig + 4]);
        }
#pragma unroll
        for (int nf = 0; nf < 2; nf++) {
            const int nb = nf * 8;
            const uint32_t b0 = __float_as_uint(Bs_s[(nb + g) * 8 + tig]);
            const uint32_t b1 = __float_as_uint(Bs_s[(nb + g) * 8 + tig + 4]);
#pragma unroll
            for (int mf = 0; mf < 2; mf++)
                mma_tf32(acc[mf][nf], af[mf][0], af[mf][1], af[mf][2],
                         af[mf][3], b0, b1);
        }
        __syncthreads();
        if (c + 4 < 128) issueChunk(c + 4, s);
        else CP_COMMIT();   // keep per-thread group counts aligned
    }

#pragma unroll
    for (int mf = 0; mf < 2; mf++) {
        const int t_lo = t0 + wm + mf * 16 + g;
#pragma unroll
        for (int nf = 0; nf < 2; nf++) {
            const int h0 = nf * 8 + 2 * tig;
            const float s0 = sb[b * HH + h0];
            const float s1 = sb[b * HH + h0 + 1];
            scores_out[((size_t)(b * HH + h0)) * TT + t_lo] = acc[mf][nf][0] + s0;
            scores_out[((size_t)(b * HH + h0 + 1)) * TT + t_lo] = acc[mf][nf][1] + s1;
            scores_out[((size_t)(b * HH + h0)) * TT + t_lo + 8] = acc[mf][nf][2] + s0;
            scores_out[((size_t)(b * HH + h0 + 1)) * TT + t_lo + 8] = acc[mf][nf][3] + s1;
        }
    }
}

// masked softmax for one (b, h)
__device__ void softmax_body(
    float* pool, const float* __restrict__ scores, const int* __restrict__ mask,
    float* __restrict__ attn_out, int b, int h) {
    float* red = pool;
    const int tid = threadIdx.x;
    const int* mrow = mask + (size_t)b * TT;
    const size_t orow = ((size_t)(b * HH + h)) * TT;

    float sloc[16];
    float lmax = -3.0e38f;
#pragma unroll
    for (int it = 0; it < 16; it++) {
        const int t = tid + it * 256;
        const float s = scores[orow + t];
        const float ms = (mrow[t] > 0) ? s : -1e30f;
        sloc[it] = ms;
        lmax = fmaxf(lmax, ms);
    }
    red[tid] = lmax;
    __syncthreads();
    for (int st = 128; st > 0; st >>= 1) {
        if (tid < st) red[tid] = fmaxf(red[tid], red[tid + st]);
        __syncthreads();
    }
    const float mx = red[0];
    __syncthreads();

    float lsum = 0.f;
#pragma unroll
    for (int it = 0; it < 16; it++) {
        const float e = __expf(sloc[it] - mx);
        sloc[it] = e;
        lsum += e;
    }
    red[tid] = lsum;
    __syncthreads();
    for (int st = 128; st > 0; st >>= 1) {
        if (tid < st) red[tid] += red[tid + st];
        __syncthreads();
    }
    const float inv = 1.0f / red[0];
#pragma unroll
    for (int it = 0; it < 16; it++)
        attn_out[orow + tid + it * 256] = sloc[it] * inv;
}

// rmix tile: r[b, :, n0..n0+63] = attn[b] @ matrix[b, :, n-slice]
#define RMB_BSTRIDE 72
#define RMB_ASTRIDE 36
#define RMB_BS (32 * RMB_BSTRIDE)
#define RMB_AS (16 * RMB_ASTRIDE)
#define RMB_STAGE (RMB_BS + RMB_AS)   // 2880 floats
__device__ void rmix_body(
    float* pool, const float* __restrict__ attn,
    const float* __restrict__ matrix, float* __restrict__ r, int b, int jn) {
    const uint32_t su0 = smem_u32(pool);
    const int tid = threadIdx.x;
    const int wid = tid >> 5;
    const int lid = tid & 31;
    const int g = lid >> 2, tig = lid & 3;
    const int n0 = jn * 64;
    const int wn = wid * 8;

    float acc[4];
#pragma unroll
    for (int q = 0; q < 4; q++) acc[q] = 0.f;

    const char* matbase = (const char*)(matrix + (size_t)b * TT * DD + n0);
    const char* attnbase = (const char*)(attn + (size_t)b * HH * TT);

    auto issueChunk = [&](int c, int s) {
        const int k0 = c * 32;
        const uint32_t bu = su0 + (uint32_t)(s * RMB_STAGE * 4);
#pragma unroll
        for (int j = 0; j < 2; j++) {
            const int u = tid + j * 256;
            const int kr = u >> 4, cu = u & 15;
            cp_async16(bu + (uint32_t)(kr * (RMB_BSTRIDE * 4) + cu * 16),
                       matbase + (size_t)(k0 + kr) * (DD * 4) + cu * 16);
        }
        if (tid < 128) {
            const int ha = tid >> 3, cu = tid & 7;
            cp_async16(bu + (uint32_t)(RMB_BS * 4) +
                           (uint32_t)(ha * (RMB_ASTRIDE * 4) + cu * 16),
                       attnbase + (size_t)ha * (TT * 4) + k0 * 4 + cu * 16);
        }
        CP_COMMIT();
    };

    issueChunk(0, 0);
    issueChunk(1, 1);
    issueChunk(2, 2);
    issueChunk(3, 3);

    for (int c = 0; c < 128; c++) {
        const int s = c & 3;
        CP_WAIT(3);
        __syncthreads();
        const float* Bs_s = pool + s * RMB_STAGE;
        const float* As_s = Bs_s + RMB_BS;
#pragma unroll
        for (int ks = 0; ks < 4; ks++) {
            const int kb = ks * 8;
            const uint32_t a0 = f2tf32(As_s[(g) * RMB_ASTRIDE + kb + tig]);
            const uint32_t a1 = f2tf32(As_s[(g + 8) * RMB_ASTRIDE + kb + tig]);
            const uint32_t a2 = f2tf32(As_s[(g) * RMB_ASTRIDE + kb + tig + 4]);
            const uint32_t a3 = f2tf32(As_s[(g + 8) * RMB_ASTRIDE + kb + tig + 4]);
            const int nc = wn + g;
            const uint32_t b0 = f2tf32(Bs_s[(kb + tig) * RMB_BSTRIDE + nc]);
            const uint32_t b1 = f2tf32(Bs_s[(kb + tig + 4) * RMB_BSTRIDE + nc]);
            mma_tf32(acc, a0, a1, a2, a3, b0, b1);
        }
        __syncthreads();
        if (c + 4 < 128) issueChunk(c + 4, s);
        else CP_COMMIT();
    }

    const int i = n0 + wn + 2 * tig;
    float2 lo = {acc[0], acc[1]};
    float2 hi = {acc[2], acc[3]};
    *(float2*)(r + ((size_t)(b * HH + g)) * DD + i) = lo;
    *(float2*)(r + ((size_t)(b * HH + g + 8)) * DD + i) = hi;
}

// ctx tile: ctx[b, jc*256 .. +255] = r[b, head(hd), :] . Wv[:, hd] + bv
__device__ void ctx_body(
    float* pool, const float* __restrict__ r, const float* __restrict__ Wv,
    const float* __restrict__ bv, float* __restrict__ ctx, int b, int jc) {
    float* r_s = pool;   // 4 heads x 1024 = 16 KB
    const int tid = threadIdx.x;
    const int hd = jc * 256 + tid;
    const int h0 = jc * 4;
    {
        const float4* src = (const float4*)(r + ((size_t)(b * HH + h0)) * DD);
        float4* dst = (float4*)r_s;
#pragma unroll
        for (int j = 0; j < 4; j++) dst[tid + j * 256] = src[tid + j * 256];
    }
    __syncthreads();
    const float* rr = r_s + ((hd >> 6) - h0) * DD;
    float acc = 0.f;
#pragma unroll 16
    for (int i = 0; i < DD; i++) acc += rr[i] * Wv[(size_t)i * DD + hd];
    ctx[(size_t)b * DD + hd] = acc + bv[hd];
}

// ---------------------------------------------------------------------------
// Fused persistent kernel: grid 444 CTAs (3/SM floor -> always all resident).
// Tickets b-major: per b -> 16 scores, 16 softmax, 16 rmix, 4 ctx.
// ---------------------------------------------------------------------------
#define POOL_BYTES (RMB_STAGE * 4 * 4)   // 46080 B (max of all bodies)
__global__ __launch_bounds__(256, 4) void fused_kernel(
    const float* __restrict__ matrix, const float* __restrict__ wqt,
    const float* __restrict__ sb, const int* __restrict__ mask,
    float* __restrict__ scores_out, float* __restrict__ attn_out,
    float* __restrict__ r, const float* __restrict__ Wv,
    const float* __restrict__ bv, float* __restrict__ ctx) {
    extern __shared__ float pool[];
    __shared__ int s_ticket;
    const int tid = threadIdx.x;

    while (true) {
        if (tid == 0) s_ticket = atomicAdd(&g_tk, 1);
        __syncthreads();
        const int t = s_ticket;
        if (t >= NTICKETS) break;
        const int b = t / TICKETS_PER_B;
        const int k = t % TICKETS_PER_B;

        if (k < 16) {
            // admission window: keep ~BWINDOW b's of matrix in flight (L2 reuse)
            if (tid == 0) {
                while (b >= ld_acquire(&g_bc) + BWINDOW) __nanosleep(512);
            }
            __syncthreads();
            scores_body(pool, matrix, wqt, sb, scores_out, b, k);
            mark_done(&g_sd[b]);
        } else if (k < 32) {
            spin_until(&g_sd[b], 16);
            softmax_body(pool, scores_out, mask, attn_out, b, k - 16);
            mark_done(&g_smd[b]);
        } else if (k < 48) {
            spin_until(&g_smd[b], 16);
            rmix_body(pool, attn_out, matrix, r, b, k - 32);
            __threadfence();
            __syncthreads();
            if (tid == 0) {
                const int v = atomicAdd(&g_rd[b], 1);
                if (v == 15) atomicAdd(&g_bc, 1);
            }
        } else {
            spin_until(&g_rd[b], 16);
            ctx_body(pool, r, Wv, bv, ctx, b, k - 48);
        }
        __syncthreads();   // protect s_ticket for next iteration
    }
}

// ---------------------------------------------------------------------------
// Launch
// ---------------------------------------------------------------------------
extern "C" void kernel_launch(void* const* d_in, const int* in_sizes, int n_in,
                              void* d_out, int out_size) {
    const float* vector = (const float*)d_in[0];
    const float* matrix = (const float*)d_in[1];
    const int*   mask   = (const int*)d_in[2];
    const float* Wq = (const float*)d_in[3];
    const float* bq = (const float*)d_in[4];
    const float* Wk = (const float*)d_in[5];
    const float* bk = (const float*)d_in[6];
    const float* Wv = (const float*)d_in[7];
    const float* bv = (const float*)d_in[8];
    const float* Wo = (const float*)d_in[9];
    const float* bo = (const float*)d_in[10];

    float* out = (float*)d_out;
    float* out_final  = out;
    float* attn_out   = out + (size_t)BB * DD;
    float* scores_out = attn_out + (size_t)BB * HH * TT;

    float *pq, *pwqt, *psb, *pr, *pctx, *ppp;
    cudaGetSymbolAddress((void**)&pq, g_q);
    cudaGetSymbolAddress((void**)&pwqt, g_wqt);
    cudaGetSymbolAddress((void**)&psb, g_sb);
    cudaGetSymbolAddress((void**)&pr, g_r);
    cudaGetSymbolAddress((void**)&pctx, g_ctx);
    cudaGetSymbolAddress((void**)&ppp, g_pp);

    cudaFuncSetAttribute(wqt_kernel,
                         cudaFuncAttributeMaxDynamicSharedMemorySize, WQT_SMEM);
    cudaFuncSetAttribute(fused_kernel,
                         cudaFuncAttributeMaxDynamicSharedMemorySize, POOL_BYTES);

    // 1: q partials (also zeroes persistent counters in block (0,0))
    dim3 rpgrid(4, BB);
    rp_part_kernel<<<rpgrid, 256>>>(vector, Wq, ppp);
    // 2: q reduce + sb
    rp_reduce_kernel<<<BB, 256>>>(ppp, bq, pq, bk, psb);
    // 3: wq~
    dim3 wgrid(4, BB);
    wqt_kernel<<<wgrid, 256, WQT_SMEM>>>(Wk, pq, pwqt);
    // 4: fused scores -> softmax -> rmix -> ctx (persistent, ticketed)
    fused_kernel<<<FUSED_GRID, 256, POOL_BYTES>>>(matrix, pwqt, psb, mask,
                                                  scores_out, attn_out, pr,
                                                  Wv, bv, pctx);
    // 5-6: out = ctx @ Wo + bo
    rp_part_kernel<<<rpgrid, 256>>>(pctx, Wo, ppp);
    rp_reduce_kernel<<<BB, 256>>>(ppp, bo, out_final, nullptr, nullptr);
}